// round 13
// baseline (speedup 1.0000x reference)
#include <cuda_runtime.h>
#include <cuda_fp16.h>
#include <cstdint>

// ---------------------------------------------------------------------------
// b=16, c=512, hw=4096
//   inter = sigmoid(depth @ rgb^T)    (512x512, K=4096, NT, 3-pass fp16 split)
//   out   = rgb + inter @ depth       (512x4096, K=512; B via ldsm.trans,
//                                      2-pass: inter_h x (depth_hi+depth_lo))
// mma.sync f16, fp32 accum.  BM=128, BN=256, BK=32, warptile 64x64,
// 3 stages, SW64 swizzle (64B rows).
// ---------------------------------------------------------------------------

#define BATCH 16
#define CDIM  512
#define HW    4096

#define BM 128
#define BN 256
#define BK 32

#define OFF_AHI 0
#define OFF_ALO 8192
#define OFF_BHI 16384
#define OFF_BLO 32768
#define STAGE   49152
#define NSTAGE  3
#define SMEM_TOTAL (NSTAGE * STAGE)   // 144 KB per CTA

// ---------------------------------------------------------------------------
// Scratch (__device__ globals; allocation-guard-safe), all fp16
// ---------------------------------------------------------------------------
__device__ __align__(128) __half g_depth_hi[BATCH * CDIM * HW];   // [b,c,s]
__device__ __align__(128) __half g_depth_lo[BATCH * CDIM * HW];
__device__ __align__(128) __half g_rgb_hi  [BATCH * CDIM * HW];   // [b,c,s]
__device__ __align__(128) __half g_rgb_lo  [BATCH * CDIM * HW];
__device__ __align__(128) __half g_inter_h [BATCH * CDIM * CDIM]; // [b,c,d]

// ---------------------------------------------------------------------------
// PTX helpers (sm_80-era; compile under plain compute_103)
// ---------------------------------------------------------------------------
__device__ __forceinline__ uint32_t smem_u32(const void* p) {
    uint32_t a;
    asm("{ .reg .u64 t; cvta.to.shared.u64 t, %1; cvt.u32.u64 %0, t; }"
        : "=r"(a) : "l"(p));
    return a;
}

__device__ __forceinline__ void cpasync16(uint32_t s, const void* g) {
    asm volatile("cp.async.cg.shared.global [%0], [%1], 16;" :: "r"(s), "l"(g));
}
#define CP_COMMIT() asm volatile("cp.async.commit_group;" ::: "memory")
#define CP_WAIT2()  asm volatile("cp.async.wait_group 2;" ::: "memory")

__device__ __forceinline__ void ldsm4(uint32_t (&r)[4], uint32_t a) {
    asm volatile("ldmatrix.sync.aligned.m8n8.x4.shared.b16 {%0,%1,%2,%3}, [%4];"
                 : "=r"(r[0]), "=r"(r[1]), "=r"(r[2]), "=r"(r[3]) : "r"(a));
}
__device__ __forceinline__ void ldsm4t(uint32_t (&r)[4], uint32_t a) {
    asm volatile("ldmatrix.sync.aligned.m8n8.x4.trans.shared.b16 {%0,%1,%2,%3}, [%4];"
                 : "=r"(r[0]), "=r"(r[1]), "=r"(r[2]), "=r"(r[3]) : "r"(a));
}

__device__ __forceinline__ void mma16816(float (&d)[4], const uint32_t (&a)[4],
                                         uint32_t b0, uint32_t b1) {
    asm volatile(
        "mma.sync.aligned.m16n8k16.row.col.f32.f16.f16.f32 "
        "{%0,%1,%2,%3},{%4,%5,%6,%7},{%8,%9},{%0,%1,%2,%3};"
        : "+f"(d[0]), "+f"(d[1]), "+f"(d[2]), "+f"(d[3])
        : "r"(a[0]), "r"(a[1]), "r"(a[2]), "r"(a[3]), "r"(b0), "r"(b1));
}

// SW64 swizzle for 64-byte rows: XOR bits[4:5] with bits[7:8].
__device__ __forceinline__ uint32_t sw(uint32_t off) {
    return off ^ ((off >> 3) & 0x30);
}

// ---------------------------------------------------------------------------
// Producers.  A: BMx32 (m-major, 64B rows).  B (BN=256):
//   MODE 0 (GEMM1): B = 256x32 n-major (64B rows); A hi+lo, B hi+lo.
//   MODE 1 (GEMM2): B = 32x256 k-major source via 8 subtiles of 32(k)x32(n);
//                   A hi ONLY, B hi+lo.
// ---------------------------------------------------------------------------
template <int MODE>
__device__ __forceinline__ void produce(
    uint32_t sb, int stage,
    const __half* __restrict__ Ahi, const __half* __restrict__ Alo,
    const __half* __restrict__ Bhi, const __half* __restrict__ Blo,
    int lda, int ldb, int kcol)
{
    const int tid = threadIdx.x;
    const uint32_t s0 = sb + stage * STAGE;
    // A tile: 128 rows x 4 chunks = 512 chunk-slots
#pragma unroll
    for (int i = 0; i < 2; ++i) {
        const int id = tid + 256 * i;
        const int row = id >> 2, c = id & 3;
        const uint32_t off = sw((uint32_t)row * 64u + (uint32_t)c * 16u);
        const size_t ga = (size_t)row * lda + kcol + c * 8;
        cpasync16(s0 + OFF_AHI + off, Ahi + ga);
        if (MODE == 0)
            cpasync16(s0 + OFF_ALO + off, Alo + ga);
    }
    // B tile: 1024 chunk-slots (hi + lo each)
#pragma unroll
    for (int i = 0; i < 4; ++i) {
        const int id = tid + 256 * i;
        uint32_t off;
        size_t gb;
        if (MODE == 0) {
            const int row = id >> 2, c = id & 3;
            off = sw((uint32_t)row * 64u + (uint32_t)c * 16u);
            gb = (size_t)row * ldb + kcol + c * 8;
        } else {
            const int h = id >> 7, k = (id >> 2) & 31, cn = id & 3;
            off = (uint32_t)h * 2048u + sw((uint32_t)k * 64u + (uint32_t)cn * 16u);
            gb = (size_t)(kcol + k) * ldb + h * 32 + cn * 8;
        }
        cpasync16(s0 + OFF_BHI + off, Bhi + gb);
        cpasync16(s0 + OFF_BLO + off, Blo + gb);
    }
    CP_COMMIT();
}

// ---------------------------------------------------------------------------
// Consumer: one stage = 2 k16 steps.
// 8 warps as 2(m) x 4(n); warp tile 64x64. acc[t:4 m16][nidx:8 n8][4].
// MODE 0: 3 passes (ah*bh, ah*bl, al*bh).  MODE 1: 2 passes (ah*bh, ah*bl).
// ---------------------------------------------------------------------------
template <int MODE>
__device__ __forceinline__ void consume(uint32_t sb, int stage,
                                        float (&acc)[4][8][4]) {
    const int tid = threadIdx.x;
    const int lane = tid & 31, wid = tid >> 5;
    const int wm = wid >> 2, wn = wid & 3;
    const uint32_t s0 = sb + stage * STAGE;

    const int a_r = lane & 15, a_c = lane >> 4;
    const int b_n = ((lane >> 4) << 3) + (lane & 7);
    const int b_c = (lane >> 3) & 1;
    const int bt_k = ((lane >> 3) & 1) * 8 + (lane & 7);
    const int bt_u = lane >> 4;

#pragma unroll
    for (int kk = 0; kk < 2; ++kk) {
        uint32_t bh[4][4], bl[4][4];
#pragma unroll
        for (int u = 0; u < 4; ++u) {
            if (MODE == 0) {
                const uint32_t off =
                    sw((uint32_t)(wn * 64 + u * 16 + b_n) * 64u +
                       (uint32_t)(kk * 2 + b_c) * 16u);
                ldsm4(bh[u], s0 + OFF_BHI + off);
                ldsm4(bl[u], s0 + OFF_BLO + off);
            } else {
                const uint32_t off = (uint32_t)(wn * 2 + (u >> 1)) * 2048u +
                    sw((uint32_t)(kk * 16 + bt_k) * 64u +
                       (uint32_t)((u & 1) * 2 + bt_u) * 16u);
                ldsm4t(bh[u], s0 + OFF_BHI + off);
                ldsm4t(bl[u], s0 + OFF_BLO + off);
            }
        }
#pragma unroll
        for (int t = 0; t < 4; ++t) {
            uint32_t ah[4], al[4];
            const uint32_t off =
                sw((uint32_t)(wm * 64 + t * 16 + a_r) * 64u +
                   (uint32_t)(kk * 2 + a_c) * 16u);
            ldsm4(ah, s0 + OFF_AHI + off);
            if (MODE == 0)
                ldsm4(al, s0 + OFF_ALO + off);
#pragma unroll
            for (int u = 0; u < 4; ++u) {
#pragma unroll
                for (int h = 0; h < 2; ++h) {
                    float (&d)[4] = acc[t][u * 2 + h];
                    mma16816(d, ah, bh[u][h * 2], bh[u][h * 2 + 1]);
                    mma16816(d, ah, bl[u][h * 2], bl[u][h * 2 + 1]);
                    if (MODE == 0)
                        mma16816(d, al, bh[u][h * 2], bh[u][h * 2 + 1]);
                }
            }
        }
    }
}

// ---------------------------------------------------------------------------
// Multistage mainloop (R8/R12 structure: two syncs/chunk, produce after
// consume into the just-drained stage).  Groups: 3 primed + 1/iter =>
// wait_group 2 at iter c guarantees chunk c has landed.
// ---------------------------------------------------------------------------
template <int MODE>
__device__ __forceinline__ void mainloop(
    uint32_t sb, float (&acc)[4][8][4],
    const __half* Ahi, const __half* Alo,
    const __half* Bhi, const __half* Blo,
    int lda, int ldb, int nch)
{
#pragma unroll
    for (int t = 0; t < 4; ++t)
#pragma unroll
        for (int n = 0; n < 8; ++n)
#pragma unroll
            for (int r = 0; r < 4; ++r) acc[t][n][r] = 0.0f;

#pragma unroll
    for (int cc = 0; cc < NSTAGE; ++cc) {
        if (cc < nch)
            produce<MODE>(sb, cc, Ahi, Alo, Bhi, Blo, lda, ldb, cc * BK);
        else
            CP_COMMIT();
    }
    for (int c = 0; c < nch; ++c) {
        CP_WAIT2();
        __syncthreads();
        consume<MODE>(sb, c % NSTAGE, acc);
        __syncthreads();
        if (c + NSTAGE < nch)
            produce<MODE>(sb, c % NSTAGE, Ahi, Alo, Bhi, Blo, lda, ldb,
                          (c + NSTAGE) * BK);
        else
            CP_COMMIT();
    }
}

__device__ __forceinline__ float sigmoidf(float x) {
    return 1.0f / (1.0f + __expf(-x));
}

// ---------------------------------------------------------------------------
// GEMM1: inter = sigmoid(depth @ rgb^T); epilogue stores inter_h fp16
// grid (2, 4, 16), 256 threads
// ---------------------------------------------------------------------------
__global__ __launch_bounds__(256)
void gemm1_tc() {
    extern __shared__ char smem[];
    const uint32_t sb = smem_u32(smem);
    const int b = blockIdx.z;
    const size_t aoff = ((size_t)b * CDIM + blockIdx.y * BM) * HW;
    const size_t boff = ((size_t)b * CDIM + blockIdx.x * BN) * HW;

    float acc[4][8][4];
    mainloop<0>(sb, acc, g_depth_hi + aoff, g_depth_lo + aoff,
                g_rgb_hi + boff, g_rgb_lo + boff, HW, HW, HW / BK);

    const int lane = threadIdx.x & 31, wid = threadIdx.x >> 5;
    const int wm = wid >> 2, wn = wid & 3;
    const int r0 = blockIdx.y * BM + wm * 64 + (lane >> 2);
    const int c0 = blockIdx.x * BN + wn * 64 + (lane & 3) * 2;
    __half* ih = g_inter_h + (size_t)b * CDIM * CDIM;
#pragma unroll
    for (int t = 0; t < 4; ++t) {
#pragma unroll
        for (int nidx = 0; nidx < 8; ++nidx) {
            const int n = c0 + nidx * 8;
#pragma unroll
            for (int half2i = 0; half2i < 2; ++half2i) {
                const int m = r0 + t * 16 + half2i * 8;
                const float v0 = sigmoidf(acc[t][nidx][half2i * 2 + 0]);
                const float v1 = sigmoidf(acc[t][nidx][half2i * 2 + 1]);
                const size_t idx = (size_t)m * CDIM + n;
                *(__half2*)(ih + idx) = __floats2half2_rn(v0, v1);
            }
        }
    }
}

// ---------------------------------------------------------------------------
// GEMM2: out = rgb + inter_h @ depth (B via ldsm.trans; 2-pass)
// grid (16, 4, 16), 256 threads
// ---------------------------------------------------------------------------
__global__ __launch_bounds__(256)
void gemm2_tc(const float* __restrict__ rgb, float* __restrict__ out) {
    extern __shared__ char smem[];
    const uint32_t sb = smem_u32(smem);
    const int b = blockIdx.z;
    const size_t aoff = ((size_t)b * CDIM + blockIdx.y * BM) * CDIM;
    const size_t boff = (size_t)b * CDIM * HW + blockIdx.x * BN;

    float acc[4][8][4];
    mainloop<1>(sb, acc, g_inter_h + aoff, (const __half*)nullptr,
                g_depth_hi + boff, g_depth_lo + boff, CDIM, HW, CDIM / BK);

    const int lane = threadIdx.x & 31, wid = threadIdx.x >> 5;
    const int wm = wid >> 2, wn = wid & 3;
    const int r0 = blockIdx.y * BM + wm * 64 + (lane >> 2);
    const int c0 = blockIdx.x * BN + wn * 64 + (lane & 3) * 2;
    const size_t base = (size_t)b * CDIM * HW;
#pragma unroll
    for (int t = 0; t < 4; ++t) {
#pragma unroll
        for (int nidx = 0; nidx < 8; ++nidx) {
            const int n = c0 + nidx * 8;
#pragma unroll
            for (int half2i = 0; half2i < 2; ++half2i) {
                const int m = r0 + t * 16 + half2i * 8;
                const size_t idx = base + (size_t)m * HW + n;
                const float2 rv = *(const float2*)(rgb + idx);
                float2 v;
                v.x = acc[t][nidx][half2i * 2 + 0] + rv.x;
                v.y = acc[t][nidx][half2i * 2 + 1] + rv.y;
                *(float2*)(out + idx) = v;
            }
        }
    }
}

// ---------------------------------------------------------------------------
// Split both inputs: fp32 -> fp16 hi/lo, 8 elems/thread each
// ---------------------------------------------------------------------------
__global__ __launch_bounds__(256)
void split_kernel(const float* __restrict__ rgb, const float* __restrict__ depth) {
    const size_t i = ((size_t)blockIdx.x * 256 + threadIdx.x) * 8;
#pragma unroll
    for (int which = 0; which < 2; ++which) {
        const float* src = which ? depth : rgb;
        __half* dh = which ? g_depth_hi : g_rgb_hi;
        __half* dl = which ? g_depth_lo : g_rgb_lo;
        float4 a = *(const float4*)(src + i);
        float4 c = *(const float4*)(src + i + 4);
        float v[8] = {a.x, a.y, a.z, a.w, c.x, c.y, c.z, c.w};
        union { __half h[8]; uint4 u; } H, L;
#pragma unroll
        for (int j = 0; j < 8; ++j) {
            __half hb = __float2half_rn(v[j]);
            H.h[j] = hb;
            L.h[j] = __float2half_rn(v[j] - __half2float(hb));
        }
        *(uint4*)(dh + i) = H.u;
        *(uint4*)(dl + i) = L.u;
    }
}

// ---------------------------------------------------------------------------
// Launch
// ---------------------------------------------------------------------------
extern "C" void kernel_launch(void* const* d_in, const int* in_sizes, int n_in,
                              void* d_out, int out_size) {
    const float* rgb   = (const float*)d_in[0];
    const float* depth = (const float*)d_in[1];
    float* out = (float*)d_out;

    cudaFuncSetAttribute(gemm1_tc,
                         cudaFuncAttributeMaxDynamicSharedMemorySize, SMEM_TOTAL);
    cudaFuncSetAttribute(gemm2_tc,
                         cudaFuncAttributeMaxDynamicSharedMemorySize, SMEM_TOTAL);

    const size_t TOT = (size_t)BATCH * CDIM * HW;   // 33,554,432
    split_kernel<<<(unsigned)(TOT / 8 / 256), 256>>>(rgb, depth);

    gemm1_tc<<<dim3(CDIM / BN, CDIM / BM, BATCH), 256, SMEM_TOTAL>>>();
    gemm2_tc<<<dim3(HW / BN, CDIM / BM, BATCH), 256, SMEM_TOTAL>>>(rgb, out);
}

// round 14
// speedup vs baseline: 1.5118x; 1.5118x over previous
#include <cuda_runtime.h>
#include <cuda_fp16.h>
#include <cstdint>

// ---------------------------------------------------------------------------
// b=16, c=512, hw=4096
//   inter = sigmoid(depth @ rgb^T)  (512x512, K=4096, NT,
//                                    2-pass: depth_hi x (rgb_hi + rgb_lo))
//   out   = rgb + inter @ depth     (512x4096, K=512; B via ldsm.trans,
//                                    1-pass: inter_h x depth_hi)
// mma.sync f16, fp32 accum.  BK=32, 3 stages, SW64 swizzle (64B rows).
// Error budget: dropped depth_lo terms contribute ~2-3e-4 rel; threshold 1e-3.
// ---------------------------------------------------------------------------

#define BATCH 16
#define CDIM  512
#define HW    4096

#define BM 128
#define BN 128
#define BK 32

#define OFF_AHI 0
#define OFF_BHI 8192
#define OFF_BLO 16384
#define STAGE0  24576                  // GEMM1: A_hi + B_hi + B_lo
#define STAGE1  16384                  // GEMM2: A_hi + B_hi
#define NSTAGE  3
#define SMEM_G1 (NSTAGE * STAGE0)      // 72 KB
#define SMEM_G2 (NSTAGE * STAGE1)      // 48 KB

// ---------------------------------------------------------------------------
// Scratch (__device__ globals; allocation-guard-safe), all fp16
// ---------------------------------------------------------------------------
__device__ __align__(128) __half g_depth_hi[BATCH * CDIM * HW];   // [b,c,s]
__device__ __align__(128) __half g_rgb_hi  [BATCH * CDIM * HW];   // [b,c,s]
__device__ __align__(128) __half g_rgb_lo  [BATCH * CDIM * HW];
__device__ __align__(128) __half g_inter_h [BATCH * CDIM * CDIM]; // [b,c,d]

// ---------------------------------------------------------------------------
// PTX helpers (sm_80-era; compile under plain compute_103)
// ---------------------------------------------------------------------------
__device__ __forceinline__ uint32_t smem_u32(const void* p) {
    uint32_t a;
    asm("{ .reg .u64 t; cvta.to.shared.u64 t, %1; cvt.u32.u64 %0, t; }"
        : "=r"(a) : "l"(p));
    return a;
}

__device__ __forceinline__ void cpasync16(uint32_t s, const void* g) {
    asm volatile("cp.async.cg.shared.global [%0], [%1], 16;" :: "r"(s), "l"(g));
}
#define CP_COMMIT() asm volatile("cp.async.commit_group;" ::: "memory")
#define CP_WAIT2()  asm volatile("cp.async.wait_group 2;" ::: "memory")

__device__ __forceinline__ void ldsm4(uint32_t (&r)[4], uint32_t a) {
    asm volatile("ldmatrix.sync.aligned.m8n8.x4.shared.b16 {%0,%1,%2,%3}, [%4];"
                 : "=r"(r[0]), "=r"(r[1]), "=r"(r[2]), "=r"(r[3]) : "r"(a));
}
__device__ __forceinline__ void ldsm4t(uint32_t (&r)[4], uint32_t a) {
    asm volatile("ldmatrix.sync.aligned.m8n8.x4.trans.shared.b16 {%0,%1,%2,%3}, [%4];"
                 : "=r"(r[0]), "=r"(r[1]), "=r"(r[2]), "=r"(r[3]) : "r"(a));
}

__device__ __forceinline__ void mma16816(float (&d)[4], const uint32_t (&a)[4],
                                         uint32_t b0, uint32_t b1) {
    asm volatile(
        "mma.sync.aligned.m16n8k16.row.col.f32.f16.f16.f32 "
        "{%0,%1,%2,%3},{%4,%5,%6,%7},{%8,%9},{%0,%1,%2,%3};"
        : "+f"(d[0]), "+f"(d[1]), "+f"(d[2]), "+f"(d[3])
        : "r"(a[0]), "r"(a[1]), "r"(a[2]), "r"(a[3]), "r"(b0), "r"(b1));
}

// SW64 swizzle for 64-byte rows: XOR bits[4:5] with bits[7:8].
__device__ __forceinline__ uint32_t sw(uint32_t off) {
    return off ^ ((off >> 3) & 0x30);
}

// ---------------------------------------------------------------------------
// Producers.  A: BMx32 (m-major, 64B rows), hi only.
//   MODE 0 (GEMM1): B = BNx32 n-major (64B rows), hi + lo.
//   MODE 1 (GEMM2): B = 32xBN k-major source via 4 subtiles of 32(k)x32(n),
//                   hi only.
// ---------------------------------------------------------------------------
template <int MODE>
__device__ __forceinline__ void produce(
    uint32_t sb, int stage,
    const __half* __restrict__ Ahi,
    const __half* __restrict__ Bhi, const __half* __restrict__ Blo,
    int lda, int ldb, int kcol)
{
    const int tid = threadIdx.x;
    const uint32_t s0 = sb + stage * (MODE == 0 ? STAGE0 : STAGE1);
#pragma unroll
    for (int i = 0; i < 2; ++i) {
        const int id = tid + 256 * i;
        // A tile (hi only): 128 rows x 4 chunks = 512 slots
        {
            const int row = id >> 2, c = id & 3;
            const uint32_t off = sw((uint32_t)row * 64u + (uint32_t)c * 16u);
            const size_t ga = (size_t)row * lda + kcol + c * 8;
            cpasync16(s0 + OFF_AHI + off, Ahi + ga);
        }
        // B tile
        if (MODE == 0) {
            const int row = id >> 2, c = id & 3;
            const uint32_t off = sw((uint32_t)row * 64u + (uint32_t)c * 16u);
            const size_t gb = (size_t)row * ldb + kcol + c * 8;
            cpasync16(s0 + OFF_BHI + off, Bhi + gb);
            cpasync16(s0 + OFF_BLO + off, Blo + gb);
        } else {
            const int h = id >> 7, k = (id >> 2) & 31, cn = id & 3;
            const uint32_t off = (uint32_t)h * 2048u +
                                 sw((uint32_t)k * 64u + (uint32_t)cn * 16u);
            const size_t gb = (size_t)(kcol + k) * ldb + h * 32 + cn * 8;
            cpasync16(s0 + OFF_BHI + off, Bhi + gb);
        }
    }
    CP_COMMIT();
}

// ---------------------------------------------------------------------------
// Consumer: one stage = 2 k16 steps.
// 8 warps as 2(m) x 4(n); warp tile 64x32. acc[t:4 m16][nidx:4 n8][4].
// MODE 0: 2 passes (ah*bh, ah*bl).  MODE 1: 1 pass (ah*bh).
// ---------------------------------------------------------------------------
template <int MODE>
__device__ __forceinline__ void consume(uint32_t sb, int stage,
                                        float (&acc)[4][4][4]) {
    const int tid = threadIdx.x;
    const int lane = tid & 31, wid = tid >> 5;
    const int wm = wid >> 2, wn = wid & 3;
    const uint32_t s0 = sb + stage * (MODE == 0 ? STAGE0 : STAGE1);

    const int a_r = lane & 15, a_c = lane >> 4;
    const int b_n = ((lane >> 4) << 3) + (lane & 7);
    const int b_c = (lane >> 3) & 1;
    const int bt_k = ((lane >> 3) & 1) * 8 + (lane & 7);
    const int bt_u = lane >> 4;

#pragma unroll
    for (int kk = 0; kk < 2; ++kk) {
        uint32_t bh[2][4], bl[2][4];
#pragma unroll
        for (int u = 0; u < 2; ++u) {
            if (MODE == 0) {
                const uint32_t off =
                    sw((uint32_t)(wn * 32 + u * 16 + b_n) * 64u +
                       (uint32_t)(kk * 2 + b_c) * 16u);
                ldsm4(bh[u], s0 + OFF_BHI + off);
                ldsm4(bl[u], s0 + OFF_BLO + off);
            } else {
                const uint32_t off = (uint32_t)wn * 2048u +
                    sw((uint32_t)(kk * 16 + bt_k) * 64u +
                       (uint32_t)(u * 2 + bt_u) * 16u);
                ldsm4t(bh[u], s0 + OFF_BHI + off);
            }
        }
#pragma unroll
        for (int t = 0; t < 4; ++t) {
            uint32_t ah[4];
            const uint32_t off =
                sw((uint32_t)(wm * 64 + t * 16 + a_r) * 64u +
                   (uint32_t)(kk * 2 + a_c) * 16u);
            ldsm4(ah, s0 + OFF_AHI + off);
#pragma unroll
            for (int u = 0; u < 2; ++u) {
#pragma unroll
                for (int h = 0; h < 2; ++h) {
                    float (&d)[4] = acc[t][u * 2 + h];
                    mma16816(d, ah, bh[u][h * 2], bh[u][h * 2 + 1]);
                    if (MODE == 0)
                        mma16816(d, ah, bl[u][h * 2], bl[u][h * 2 + 1]);
                }
            }
        }
    }
}

// ---------------------------------------------------------------------------
// Multistage mainloop (R8/R12 structure: two syncs/chunk, produce after
// consume into the just-drained stage).  Groups: 3 primed + 1/iter =>
// wait_group 2 at iter c guarantees chunk c has landed.
// ---------------------------------------------------------------------------
template <int MODE>
__device__ __forceinline__ void mainloop(
    uint32_t sb, float (&acc)[4][4][4],
    const __half* Ahi, const __half* Bhi, const __half* Blo,
    int lda, int ldb, int nch)
{
#pragma unroll
    for (int t = 0; t < 4; ++t)
#pragma unroll
        for (int n = 0; n < 4; ++n)
#pragma unroll
            for (int r = 0; r < 4; ++r) acc[t][n][r] = 0.0f;

#pragma unroll
    for (int cc = 0; cc < NSTAGE; ++cc) {
        if (cc < nch)
            produce<MODE>(sb, cc, Ahi, Bhi, Blo, lda, ldb, cc * BK);
        else
            CP_COMMIT();
    }
    for (int c = 0; c < nch; ++c) {
        CP_WAIT2();
        __syncthreads();
        consume<MODE>(sb, c % NSTAGE, acc);
        __syncthreads();
        if (c + NSTAGE < nch)
            produce<MODE>(sb, c % NSTAGE, Ahi, Bhi, Blo, lda, ldb,
                          (c + NSTAGE) * BK);
        else
            CP_COMMIT();
    }
}

__device__ __forceinline__ float sigmoidf(float x) {
    return 1.0f / (1.0f + __expf(-x));
}

// ---------------------------------------------------------------------------
// GEMM1: inter = sigmoid(depth_hi @ (rgb_hi + rgb_lo)^T); stores inter_h fp16
// grid (4, 4, 16), 256 threads
// ---------------------------------------------------------------------------
__global__ __launch_bounds__(256, 2)
void gemm1_tc() {
    extern __shared__ char smem[];
    const uint32_t sb = smem_u32(smem);
    const int b = blockIdx.z;
    const size_t aoff = ((size_t)b * CDIM + blockIdx.y * BM) * HW;
    const size_t boff = ((size_t)b * CDIM + blockIdx.x * BN) * HW;

    float acc[4][4][4];
    mainloop<0>(sb, acc, g_depth_hi + aoff,
                g_rgb_hi + boff, g_rgb_lo + boff, HW, HW, HW / BK);

    const int lane = threadIdx.x & 31, wid = threadIdx.x >> 5;
    const int wm = wid >> 2, wn = wid & 3;
    const int r0 = blockIdx.y * BM + wm * 64 + (lane >> 2);
    const int c0 = blockIdx.x * BN + wn * 32 + (lane & 3) * 2;
    __half* ih = g_inter_h + (size_t)b * CDIM * CDIM;
#pragma unroll
    for (int t = 0; t < 4; ++t) {
#pragma unroll
        for (int nidx = 0; nidx < 4; ++nidx) {
            const int n = c0 + nidx * 8;
#pragma unroll
            for (int half2i = 0; half2i < 2; ++half2i) {
                const int m = r0 + t * 16 + half2i * 8;
                const float v0 = sigmoidf(acc[t][nidx][half2i * 2 + 0]);
                const float v1 = sigmoidf(acc[t][nidx][half2i * 2 + 1]);
                const size_t idx = (size_t)m * CDIM + n;
                *(__half2*)(ih + idx) = __floats2half2_rn(v0, v1);
            }
        }
    }
}

// ---------------------------------------------------------------------------
// GEMM2: out = rgb + inter_h @ depth_hi (B via ldsm.trans; 1-pass)
// grid (32, 4, 16), 256 threads
// ---------------------------------------------------------------------------
__global__ __launch_bounds__(256, 2)
void gemm2_tc(const float* __restrict__ rgb, float* __restrict__ out) {
    extern __shared__ char smem[];
    const uint32_t sb = smem_u32(smem);
    const int b = blockIdx.z;
    const size_t aoff = ((size_t)b * CDIM + blockIdx.y * BM) * CDIM;
    const size_t boff = (size_t)b * CDIM * HW + blockIdx.x * BN;

    float acc[4][4][4];
    mainloop<1>(sb, acc, g_inter_h + aoff,
                g_depth_hi + boff, (const __half*)nullptr, CDIM, HW, CDIM / BK);

    const int lane = threadIdx.x & 31, wid = threadIdx.x >> 5;
    const int wm = wid >> 2, wn = wid & 3;
    const int r0 = blockIdx.y * BM + wm * 64 + (lane >> 2);
    const int c0 = blockIdx.x * BN + wn * 32 + (lane & 3) * 2;
    const size_t base = (size_t)b * CDIM * HW;
#pragma unroll
    for (int t = 0; t < 4; ++t) {
#pragma unroll
        for (int nidx = 0; nidx < 4; ++nidx) {
            const int n = c0 + nidx * 8;
#pragma unroll
            for (int half2i = 0; half2i < 2; ++half2i) {
                const int m = r0 + t * 16 + half2i * 8;
                const size_t idx = base + (size_t)m * HW + n;
                const float2 rv = *(const float2*)(rgb + idx);
                float2 v;
                v.x = acc[t][nidx][half2i * 2 + 0] + rv.x;
                v.y = acc[t][nidx][half2i * 2 + 1] + rv.y;
                *(float2*)(out + idx) = v;
            }
        }
    }
}

// ---------------------------------------------------------------------------
// Split: rgb -> hi+lo fp16, depth -> hi fp16.  8 elems/thread each.
// ---------------------------------------------------------------------------
__global__ __launch_bounds__(256)
void split_kernel(const float* __restrict__ rgb, const float* __restrict__ depth) {
    const size_t i = ((size_t)blockIdx.x * 256 + threadIdx.x) * 8;
    // rgb: hi + lo
    {
        float4 a = *(const float4*)(rgb + i);
        float4 c = *(const float4*)(rgb + i + 4);
        float v[8] = {a.x, a.y, a.z, a.w, c.x, c.y, c.z, c.w};
        union { __half h[8]; uint4 u; } H, L;
#pragma unroll
        for (int j = 0; j < 8; ++j) {
            __half hb = __float2half_rn(v[j]);
            H.h[j] = hb;
            L.h[j] = __float2half_rn(v[j] - __half2float(hb));
        }
        *(uint4*)(g_rgb_hi + i) = H.u;
        *(uint4*)(g_rgb_lo + i) = L.u;
    }
    // depth: hi only
    {
        float4 a = *(const float4*)(depth + i);
        float4 c = *(const float4*)(depth + i + 4);
        float v[8] = {a.x, a.y, a.z, a.w, c.x, c.y, c.z, c.w};
        union { __half h[8]; uint4 u; } H;
#pragma unroll
        for (int j = 0; j < 8; ++j)
            H.h[j] = __float2half_rn(v[j]);
        *(uint4*)(g_depth_hi + i) = H.u;
    }
}

// ---------------------------------------------------------------------------
// Launch
// ---------------------------------------------------------------------------
extern "C" void kernel_launch(void* const* d_in, const int* in_sizes, int n_in,
                              void* d_out, int out_size) {
    const float* rgb   = (const float*)d_in[0];
    const float* depth = (const float*)d_in[1];
    float* out = (float*)d_out;

    cudaFuncSetAttribute(gemm1_tc,
                         cudaFuncAttributeMaxDynamicSharedMemorySize, SMEM_G1);
    cudaFuncSetAttribute(gemm2_tc,
                         cudaFuncAttributeMaxDynamicSharedMemorySize, SMEM_G2);

    const size_t TOT = (size_t)BATCH * CDIM * HW;   // 33,554,432
    split_kernel<<<(unsigned)(TOT / 8 / 256), 256>>>(rgb, depth);

    gemm1_tc<<<dim3(CDIM / BN, CDIM / BM, BATCH), 256, SMEM_G1>>>();
    gemm2_tc<<<dim3(HW / BN, CDIM / BM, BATCH), 256, SMEM_G2>>>(rgb, out);
}